// round 14
// baseline (speedup 1.0000x reference)
#include <cuda_runtime.h>
#include <cuda_bf16.h>
#include <cstdint>

// Koopman rollout via warp-level HMMA, register-resident weights, 16 warps/CTA.
// 128 CTAs x 512 threads; CTA owns 32 rows (2 row-groups x 16), 4 warps/SMSP.
// Register-balanced asymmetric feature split (~56 B-frag regs per warp):
//   Type A (w 0-7):  MMA1 tiles {2w,2w+1} (cols 16w..16w+15) + MMA2-real tile w
//   Type B (w 8-15): MMA1 tile 16+wb (col 128+8wb)           + MMA2-complex tiles {2wb,2wb+1}
// B-fragments loaded once via ldmatrix; no weight SMEM reads in the time loop.
// Activation frags exchanged via per-lane SMEM rows (52-u32 stride, conflict-free).
// Transcendentals are degree-3 Taylor polys (|arg| <= ~0.02).

#define SMEM_BYTES 148992u
#define OFF_W1  0u        // [192 n][k stride 400B bf16]   76800 B (init staging)
#define OFF_W2C 76800u    // [128 n][k stride 272B]        34816 B (init staging)
#define OFF_W2R 111616u   // [64 n][k stride 144B]          9216 B (init staging)
#define OFF_B1  120832u   // f32[192]
#define OFF_B2  121600u   // f32[192]
#define OFF_YB  122368u   // y frags: [2 grp][32 lane][52 u32]  13312 B
#define OFF_HB  135680u   // h1 frags: same                      13312 B

__device__ __forceinline__ unsigned smem_u32(const void* p) {
    unsigned a;
    asm("{ .reg .u64 t; cvta.to.shared.u64 t, %1; cvt.u32.u64 %0, t; }"
        : "=r"(a) : "l"(p));
    return a;
}
__device__ __forceinline__ unsigned pbf(float lo, float hi) {
    unsigned r;
    asm("cvt.rn.bf16x2.f32 %0, %1, %2;" : "=r"(r) : "f"(hi), "f"(lo));
    return r;
}
__device__ __forceinline__ float exp3(float z) {
    return 1.0f + z * (1.0f + z * (0.5f + z * 0.16666667f));
}

#define LDSM4(r0, r1, r2, r3, a) \
    asm volatile("ldmatrix.sync.aligned.m8n8.x4.shared.b16 {%0,%1,%2,%3}, [%4];" \
                 : "=r"(r0), "=r"(r1), "=r"(r2), "=r"(r3) : "r"(a))
#define LDSM2(r0, r1, a) \
    asm volatile("ldmatrix.sync.aligned.m8n8.x2.shared.b16 {%0,%1}, [%2];" \
                 : "=r"(r0), "=r"(r1) : "r"(a))

#define MMA(d, a0, a1, a2, a3, b0, b1) \
    asm volatile("mma.sync.aligned.m16n8k16.row.col.f32.bf16.bf16.f32 " \
                 "{%0,%1,%2,%3},{%4,%5,%6,%7},{%8,%9},{%0,%1,%2,%3};" \
                 : "+f"((d)[0]), "+f"((d)[1]), "+f"((d)[2]), "+f"((d)[3]) \
                 : "r"(a0), "r"(a1), "r"(a2), "r"(a3), "r"(b0), "r"(b1))

__global__ void __launch_bounds__(512, 1)
koopman_w16_kernel(const float* __restrict__ x,
                   const float* __restrict__ cW1, const float* __restrict__ cb1,
                   const float* __restrict__ cW2, const float* __restrict__ cb2,
                   const float* __restrict__ rW1, const float* __restrict__ rb1,
                   const float* __restrict__ rW2, const float* __restrict__ rb2,
                   float* __restrict__ out)
{
    extern __shared__ unsigned char smem[];
    const unsigned sb = smem_u32(smem);
    const int tid = threadIdx.x;
    const int lane = tid & 31;
    const int w = tid >> 5;            // 0..15
    const bool isA = (w < 8);
    const int wb = w & 7;

    float* b1f = (float*)(smem + OFF_B1);
    float* b2f = (float*)(smem + OFF_B2);

    // ---- one-time: weights -> bf16 SMEM (staging for ldmatrix) ----
    for (int idx = tid; idx < 192 * 96; idx += 512) {
        int n = idx / 96, k = 2 * (idx - n * 96);
        const float* s = (n < 128) ? (cW1 + n * 192 + k) : (rW1 + (n - 128) * 192 + k);
        *(unsigned*)(smem + OFF_W1 + n * 400 + k * 2) = pbf(s[0], s[1]);
    }
    for (int idx = tid; idx < 128 * 64; idx += 512) {
        int n = idx >> 6, k = 2 * (idx & 63);
        *(unsigned*)(smem + OFF_W2C + n * 272 + k * 2) =
            pbf(cW2[n * 128 + k], cW2[n * 128 + k + 1]);
    }
    for (int idx = tid; idx < 64 * 32; idx += 512) {
        int n = idx >> 5, k = 2 * (idx & 31);
        *(unsigned*)(smem + OFF_W2R + n * 144 + k * 2) =
            pbf(rW2[n * 64 + k], rW2[n * 64 + k + 1]);
    }
    for (int i = tid; i < 192; i += 512) {
        b1f[i] = (i < 128) ? cb1[i] : rb1[i - 128];
        b2f[i] = (i < 128) ? cb2[i] : rb2[i - 128];
    }
    __syncthreads();

    // ---- per-lane constants ----
    const int colb = 2 * (lane & 3);
    const int lrow = (lane & 7) + ((lane >> 4) << 3);
    const unsigned lkb = ((lane >> 3) & 1) * 16;

    // ---- persistent B-fragments in registers (balanced ~56/warp) ----
    unsigned B1[12][2][2];   // A: 2 tiles; B: only [k][0]
    unsigned B2[8][2][2];    // A: real, only [0..3][0]; B: complex [0..7][0..1]
    if (isA) {
        const unsigned aW1 = sb + OFF_W1 + (16 * w + lrow) * 400 + lkb;
#pragma unroll
        for (int k = 0; k < 12; ++k)
            LDSM4(B1[k][0][0], B1[k][0][1], B1[k][1][0], B1[k][1][1], aW1 + k * 32);
        const unsigned aW2 = sb + OFF_W2R + (8 * w + (lane & 7)) * 144 + lkb;
#pragma unroll
        for (int k = 0; k < 4; ++k)
            LDSM2(B2[k][0][0], B2[k][0][1], aW2 + k * 32);
    } else {
        const unsigned aW1 = sb + OFF_W1 + (128 + 8 * wb + (lane & 7)) * 400 + lkb;
#pragma unroll
        for (int k = 0; k < 12; ++k)
            LDSM2(B1[k][0][0], B1[k][0][1], aW1 + k * 32);
        const unsigned aW2 = sb + OFF_W2C + (16 * wb + lrow) * 272 + lkb;
#pragma unroll
        for (int k = 0; k < 8; ++k)
            LDSM4(B2[k][0][0], B2[k][0][1], B2[k][1][0], B2[k][1][1], aW2 + k * 32);
    }

    // ---- owned columns / bias registers ----
    // MMA1 (h) ownership: A = cols 16w..16w+15 ; B = col 128+8wb..+7
    // MMA2 (y) ownership: A = real col 128+8w..+7 ; B = complex cols 16wb..16wb+15
    float2 bc1[2], bc2s[2];
    if (isA) {
#pragma unroll
        for (int n = 0; n < 2; ++n)
            bc1[n] = *(const float2*)(b1f + 16 * w + 8 * n + colb);
        float2 b = *(const float2*)(b2f + 128 + 8 * w + colb);
        bc2s[0] = make_float2(0.01f * b.x, 0.01f * b.y);
    } else {
        bc1[0] = *(const float2*)(b1f + 128 + 8 * wb + colb);
#pragma unroll
        for (int n = 0; n < 2; ++n) {
            float2 b = *(const float2*)(b2f + 16 * wb + 8 * n + colb);
            bc2s[n] = make_float2(0.01f * b.x, 0.01f * b.y);
        }
    }

    // ---- frag exchange rows (52-u32 stride: conflict-free LDS.128) ----
    unsigned* ybg[2];
    unsigned* hbg[2];
#pragma unroll
    for (int g = 0; g < 2; ++g) {
        ybg[g] = (unsigned*)(smem + OFF_YB) + (g * 32 + lane) * 52;
        hbg[g] = (unsigned*)(smem + OFF_HB) + (g * 32 + lane) * 52;
    }

    // ---- y master state ----
    int rows[2];
    rows[0] = blockIdx.x * 32 + (lane >> 2);
    rows[1] = rows[0] + 16;
    float ym[2][2][4];   // A: only [0][g]; B: [0..1][g]
#pragma unroll
    for (int g = 0; g < 2; ++g) {
        const float* x0 = x + (size_t)rows[g] * 12288;
        const float* x1 = x0 + 8 * 12288;
        if (isA) {
            int col = 128 + 8 * w + colb;
            float2 v0 = *(const float2*)(x0 + col);
            float2 v1 = *(const float2*)(x1 + col);
            ym[0][g][0] = v0.x; ym[0][g][1] = v0.y;
            ym[0][g][2] = v1.x; ym[0][g][3] = v1.y;
            uint2 f;
            f.x = pbf(v0.x, v0.y);
            f.y = pbf(v1.x, v1.y);
            *(uint2*)(ybg[g] + 32 + 2 * w) = f;
        } else {
#pragma unroll
            for (int n = 0; n < 2; ++n) {
                int col = 16 * wb + 8 * n + colb;
                float2 v0 = *(const float2*)(x0 + col);
                float2 v1 = *(const float2*)(x1 + col);
                ym[n][g][0] = v0.x; ym[n][g][1] = v0.y;
                ym[n][g][2] = v1.x; ym[n][g][3] = v1.y;
            }
            uint4 f;
            f.x = pbf(ym[0][g][0], ym[0][g][1]);
            f.y = pbf(ym[0][g][2], ym[0][g][3]);
            f.z = pbf(ym[1][g][0], ym[1][g][1]);
            f.w = pbf(ym[1][g][2], ym[1][g][3]);
            *(uint4*)(ybg[g] + 4 * wb) = f;
        }
    }
    __syncthreads();

    float a1[2][4], a2[2][4];

    auto mma1 = [&](const unsigned* yb) {
        if (isA) {
#pragma unroll
            for (int n = 0; n < 2; ++n)
#pragma unroll
                for (int v = 0; v < 4; ++v) a1[n][v] = 0.0f;
#pragma unroll
            for (int k = 0; k < 12; ++k) {
                uint4 av = *(const uint4*)(yb + 4 * k);
                MMA(a1[0], av.x, av.y, av.z, av.w, B1[k][0][0], B1[k][0][1]);
                MMA(a1[1], av.x, av.y, av.z, av.w, B1[k][1][0], B1[k][1][1]);
            }
        } else {
#pragma unroll
            for (int v = 0; v < 4; ++v) a1[0][v] = 0.0f;
#pragma unroll
            for (int k = 0; k < 12; ++k) {
                uint4 av = *(const uint4*)(yb + 4 * k);
                MMA(a1[0], av.x, av.y, av.z, av.w, B1[k][0][0], B1[k][0][1]);
            }
        }
    };
    auto pubh = [&](unsigned* hb) {
        if (isA) {
            uint4 f;
            f.x = pbf(fmaxf(a1[0][0] + bc1[0].x, 0.0f), fmaxf(a1[0][1] + bc1[0].y, 0.0f));
            f.y = pbf(fmaxf(a1[0][2] + bc1[0].x, 0.0f), fmaxf(a1[0][3] + bc1[0].y, 0.0f));
            f.z = pbf(fmaxf(a1[1][0] + bc1[1].x, 0.0f), fmaxf(a1[1][1] + bc1[1].y, 0.0f));
            f.w = pbf(fmaxf(a1[1][2] + bc1[1].x, 0.0f), fmaxf(a1[1][3] + bc1[1].y, 0.0f));
            *(uint4*)(hb + 4 * w) = f;
        } else {
            uint2 f;
            f.x = pbf(fmaxf(a1[0][0] + bc1[0].x, 0.0f), fmaxf(a1[0][1] + bc1[0].y, 0.0f));
            f.y = pbf(fmaxf(a1[0][2] + bc1[0].x, 0.0f), fmaxf(a1[0][3] + bc1[0].y, 0.0f));
            *(uint2*)(hb + 32 + 2 * wb) = f;
        }
    };
    auto mma2 = [&](const unsigned* hb) {
        if (isA) {   // real head: h cols 128..191 (u32 32..47), K=64
#pragma unroll
            for (int v = 0; v < 4; ++v) a2[0][v] = 0.0f;
#pragma unroll
            for (int k = 0; k < 4; ++k) {
                uint4 av = *(const uint4*)(hb + 32 + 4 * k);
                MMA(a2[0], av.x, av.y, av.z, av.w, B2[k][0][0], B2[k][0][1]);
            }
        } else {     // complex head: h cols 0..127, K=128
#pragma unroll
            for (int n = 0; n < 2; ++n)
#pragma unroll
                for (int v = 0; v < 4; ++v) a2[n][v] = 0.0f;
#pragma unroll
            for (int k = 0; k < 8; ++k) {
                uint4 av = *(const uint4*)(hb + 4 * k);
                MMA(a2[0], av.x, av.y, av.z, av.w, B2[k][0][0], B2[k][0][1]);
                MMA(a2[1], av.x, av.y, av.z, av.w, B2[k][1][0], B2[k][1][1]);
            }
        }
    };
    auto epi = [&](int g, int t, unsigned* yb) {
        float* o0 = out + (size_t)rows[g] * 12288 + t * 192;
        float* o1 = o0 + 8 * 12288;
        if (isA) {   // real diagonal, 1 tile
            int col = 128 + 8 * w + colb;
            ym[0][g][0] *= exp3(fmaf(a2[0][0], 0.01f, bc2s[0].x));
            ym[0][g][1] *= exp3(fmaf(a2[0][1], 0.01f, bc2s[0].y));
            ym[0][g][2] *= exp3(fmaf(a2[0][2], 0.01f, bc2s[0].x));
            ym[0][g][3] *= exp3(fmaf(a2[0][3], 0.01f, bc2s[0].y));
            *(float2*)(o0 + col) = make_float2(ym[0][g][0], ym[0][g][1]);
            *(float2*)(o1 + col) = make_float2(ym[0][g][2], ym[0][g][3]);
            uint2 f;
            f.x = pbf(ym[0][g][0], ym[0][g][1]);
            f.y = pbf(ym[0][g][2], ym[0][g][3]);
            *(uint2*)(yb + 32 + 2 * w) = f;
        } else {     // complex pairs, 2 tiles: even col = mu, odd = omega
#pragma unroll
            for (int n = 0; n < 2; ++n) {
                float zm0 = fmaf(a2[n][0], 0.01f, bc2s[n].x);
                float zo0 = fmaf(a2[n][1], 0.01f, bc2s[n].y);
                float e0 = exp3(zm0);
                float q0 = zo0 * zo0;
                float s0 = zo0 * (1.0f - q0 * 0.16666667f);
                float c0 = 1.0f - q0 * (0.5f - q0 * (1.0f / 24.0f));
                float ye = ym[n][g][0], yo = ym[n][g][1];
                ym[n][g][0] = e0 * (c0 * ye - s0 * yo);
                ym[n][g][1] = e0 * (s0 * ye + c0 * yo);
                float zm1 = fmaf(a2[n][2], 0.01f, bc2s[n].x);
                float zo1 = fmaf(a2[n][3], 0.01f, bc2s[n].y);
                float e1 = exp3(zm1);
                float q1 = zo1 * zo1;
                float s1 = zo1 * (1.0f - q1 * 0.16666667f);
                float c1 = 1.0f - q1 * (0.5f - q1 * (1.0f / 24.0f));
                ye = ym[n][g][2]; yo = ym[n][g][3];
                ym[n][g][2] = e1 * (c1 * ye - s1 * yo);
                ym[n][g][3] = e1 * (s1 * ye + c1 * yo);
                int col = 16 * wb + 8 * n + colb;
                *(float2*)(o0 + col) = make_float2(ym[n][g][0], ym[n][g][1]);
                *(float2*)(o1 + col) = make_float2(ym[n][g][2], ym[n][g][3]);
            }
            uint4 f;
            f.x = pbf(ym[0][g][0], ym[0][g][1]);
            f.y = pbf(ym[0][g][2], ym[0][g][3]);
            f.z = pbf(ym[1][g][0], ym[1][g][1]);
            f.w = pbf(ym[1][g][2], ym[1][g][3]);
            *(uint4*)(yb + 4 * wb) = f;
        }
    };

    // ---- prologue: h(g0) for t=0 ----
    mma1(ybg[0]);
    pubh(hbg[0]);
    __syncthreads();

#pragma unroll 1
    for (int t = 0; t < 64; ++t) {
        // section 1: consume H0, Y1; produce Y0 (t), H1 (t)
        mma2(hbg[0]);
        mma1(ybg[1]);
        epi(0, t, ybg[0]);
        pubh(hbg[1]);
        __syncthreads();
        // section 2: consume H1, Y0; produce Y1 (t), H0 (t+1)
        mma2(hbg[1]);
        mma1(ybg[0]);
        epi(1, t, ybg[1]);
        pubh(hbg[0]);
        __syncthreads();
    }
}

extern "C" void kernel_launch(void* const* d_in, const int* in_sizes, int n_in,
                              void* d_out, int out_size)
{
    (void)in_sizes; (void)n_in; (void)out_size;
    cudaFuncSetAttribute(koopman_w16_kernel,
                         cudaFuncAttributeMaxDynamicSharedMemorySize, SMEM_BYTES);
    koopman_w16_kernel<<<128, 512, SMEM_BYTES>>>(
        (const float*)d_in[0],
        (const float*)d_in[1], (const float*)d_in[2],
        (const float*)d_in[3], (const float*)d_in[4],
        (const float*)d_in[5], (const float*)d_in[6],
        (const float*)d_in[7], (const float*)d_in[8],
        (float*)d_out);
}